// round 2
// baseline (speedup 1.0000x reference)
#include <cuda_runtime.h>
#include <math.h>

#define B_   2
#define S_   2048
#define DIN  2048
#define H_   32
#define G_   8
#define R_   4
#define HD   64
#define DKV  512            // G_*HD
#define MROWS (B_*S_)       // 4096

// Scratch (allocation-free rule: __device__ globals)
__device__ float g_Q[(size_t)MROWS*DIN];    // [b*s][h*64+d]
__device__ float g_K[(size_t)MROWS*DKV];    // [b*s][g*64+d]
__device__ float g_V[(size_t)MROWS*DKV];
__device__ float g_ctx[(size_t)MROWS*DIN];

// ---------------------------------------------------------------------------
// C[M,N] = A[M,K] @ W[N,K]^T   (torch-style linear)
// 128x128 tile, TK=16, 256 threads, 8x8 per-thread micro-tile.
// Smem stored k-major (As[kk][row]) so compute loads are float4.
// ---------------------------------------------------------------------------
__global__ __launch_bounds__(256) void gemm_nt128(
    const float* __restrict__ A, const float* __restrict__ W,
    float* __restrict__ C, int M, int N, int K)
{
    __shared__ float As[16][132];
    __shared__ float Ws[16][132];

    const int bm = blockIdx.y * 128;
    const int bn = blockIdx.x * 128;
    const int tid = threadIdx.x;
    const int tr = tid >> 4;     // 0..15
    const int tc = tid & 15;     // 0..15

    float acc[8][8];
#pragma unroll
    for (int i = 0; i < 8; i++)
#pragma unroll
        for (int j = 0; j < 8; j++) acc[i][j] = 0.f;

    for (int k0 = 0; k0 < K; k0 += 16) {
        // Load 128x16 of A and W: 512 float4 each, 2 per thread per matrix.
#pragma unroll
        for (int l = 0; l < 2; l++) {
            int f  = tid + l * 256;          // 0..511
            int r  = f >> 2;                 // 4 float4 per row
            int kc = (f & 3) * 4;
            float4 av = *(const float4*)&A[(size_t)(bm + r) * K + k0 + kc];
            As[kc + 0][r] = av.x; As[kc + 1][r] = av.y;
            As[kc + 2][r] = av.z; As[kc + 3][r] = av.w;
            float4 wv = *(const float4*)&W[(size_t)(bn + r) * K + k0 + kc];
            Ws[kc + 0][r] = wv.x; Ws[kc + 1][r] = wv.y;
            Ws[kc + 2][r] = wv.z; Ws[kc + 3][r] = wv.w;
        }
        __syncthreads();

#pragma unroll
        for (int kk = 0; kk < 16; kk++) {
            float a[8], w[8];
            *(float4*)(a)     = *(float4*)&As[kk][tr * 8];
            *(float4*)(a + 4) = *(float4*)&As[kk][tr * 8 + 4];
            *(float4*)(w)     = *(float4*)&Ws[kk][tc * 8];
            *(float4*)(w + 4) = *(float4*)&Ws[kk][tc * 8 + 4];
#pragma unroll
            for (int i = 0; i < 8; i++)
#pragma unroll
                for (int j = 0; j < 8; j++)
                    acc[i][j] = fmaf(a[i], w[j], acc[i][j]);
        }
        __syncthreads();
    }

#pragma unroll
    for (int i = 0; i < 8; i++) {
        size_t row = (size_t)(bm + tr * 8 + i);
        float4 o0 = make_float4(acc[i][0], acc[i][1], acc[i][2], acc[i][3]);
        float4 o1 = make_float4(acc[i][4], acc[i][5], acc[i][6], acc[i][7]);
        *(float4*)&C[row * N + bn + tc * 8]     = o0;
        *(float4*)&C[row * N + bn + tc * 8 + 4] = o1;
    }
}

// ---------------------------------------------------------------------------
// Flash attention (causal, fp32). One CTA per (q-tile of 64 rows, head, batch).
// 256 threads: (tr,tc) 16x16 grid, each thread owns 4 rows x 4 cols/dims.
// Smem: Qt[d][r], Kt[d][c] (k-major for float4 QK loads), Vs[k][d], Ps[r][c].
// ---------------------------------------------------------------------------
__global__ __launch_bounds__(256) void attn_kernel()
{
    extern __shared__ float sm[];
    float* Qt = sm;                 // 64*68
    float* Kt = Qt + 64 * 68;
    float* Vs = Kt + 64 * 68;       // Vs[k*68 + d]
    float* Ps = Vs + 64 * 68;       // Ps[r*68 + c]

    const int qt = blockIdx.x;
    const int h  = blockIdx.y;
    const int b  = blockIdx.z;
    const int g  = h / R_;
    const int tid = threadIdx.x;
    const int tr = tid >> 4;
    const int tc = tid & 15;
    const float scale = 0.125f;     // 1/sqrt(64)

    // Load Q tile (64 rows x 64 dims) transposed into Qt[d][r]
#pragma unroll
    for (int l = 0; l < 4; l++) {
        int f  = tid + l * 256;        // 0..1023 float4s
        int r  = f >> 4;               // 16 float4 per row
        int dc = (f & 15) * 4;
        float4 v = *(const float4*)&g_Q[(size_t)(b * S_ + qt * 64 + r) * DIN + h * HD + dc];
        Qt[(dc + 0) * 68 + r] = v.x; Qt[(dc + 1) * 68 + r] = v.y;
        Qt[(dc + 2) * 68 + r] = v.z; Qt[(dc + 3) * 68 + r] = v.w;
    }

    float m[4], lsum[4], acc[4][4];
#pragma unroll
    for (int i = 0; i < 4; i++) {
        m[i] = -1e30f; lsum[i] = 0.f;
#pragma unroll
        for (int j = 0; j < 4; j++) acc[i][j] = 0.f;
    }

    for (int kt = 0; kt <= qt; kt++) {
        __syncthreads();   // prev PV done (and Qt visible on first iter)
        // Load K tile transposed, V tile natural
#pragma unroll
        for (int l = 0; l < 4; l++) {
            int f  = tid + l * 256;
            int r  = f >> 4;
            int dc = (f & 15) * 4;
            size_t src = (size_t)(b * S_ + kt * 64 + r) * DKV + g * HD + dc;
            float4 kv = *(const float4*)&g_K[src];
            Kt[(dc + 0) * 68 + r] = kv.x; Kt[(dc + 1) * 68 + r] = kv.y;
            Kt[(dc + 2) * 68 + r] = kv.z; Kt[(dc + 3) * 68 + r] = kv.w;
            float4 vv = *(const float4*)&g_V[src];
            *(float4*)&Vs[r * 68 + dc] = vv;
        }
        __syncthreads();

        // S = Q @ K^T
        float s[4][4];
#pragma unroll
        for (int i = 0; i < 4; i++)
#pragma unroll
            for (int j = 0; j < 4; j++) s[i][j] = 0.f;
#pragma unroll 8
        for (int dd = 0; dd < 64; dd++) {
            float4 a = *(float4*)&Qt[dd * 68 + tr * 4];
            float4 w = *(float4*)&Kt[dd * 68 + tc * 4];
            float av[4] = {a.x, a.y, a.z, a.w};
            float wv[4] = {w.x, w.y, w.z, w.w};
#pragma unroll
            for (int i = 0; i < 4; i++)
#pragma unroll
                for (int j = 0; j < 4; j++)
                    s[i][j] = fmaf(av[i], wv[j], s[i][j]);
        }

        // scale + causal mask (only diagonal tile needs it)
#pragma unroll
        for (int i = 0; i < 4; i++)
#pragma unroll
            for (int j = 0; j < 4; j++) {
                s[i][j] *= scale;
                if (kt == qt && (tc * 4 + j) > (tr * 4 + i)) s[i][j] = -1e30f;
            }

        // Online softmax update (reduce across the 16 tc-lanes owning each row)
#pragma unroll
        for (int i = 0; i < 4; i++) {
            float rmax = fmaxf(fmaxf(s[i][0], s[i][1]), fmaxf(s[i][2], s[i][3]));
#pragma unroll
            for (int off = 8; off > 0; off >>= 1)
                rmax = fmaxf(rmax, __shfl_xor_sync(0xffffffffu, rmax, off));
            float mn = fmaxf(m[i], rmax);
            float alpha = __expf(m[i] - mn);
            float4 p;
            p.x = __expf(s[i][0] - mn);
            p.y = __expf(s[i][1] - mn);
            p.z = __expf(s[i][2] - mn);
            p.w = __expf(s[i][3] - mn);
            float rsum = p.x + p.y + p.z + p.w;
#pragma unroll
            for (int off = 8; off > 0; off >>= 1)
                rsum += __shfl_xor_sync(0xffffffffu, rsum, off);
            lsum[i] = lsum[i] * alpha + rsum;
            m[i] = mn;
#pragma unroll
            for (int j = 0; j < 4; j++) acc[i][j] *= alpha;
            *(float4*)&Ps[(tr * 4 + i) * 68 + tc * 4] = p;
        }
        __syncthreads();

        // acc += P @ V
#pragma unroll 8
        for (int kk = 0; kk < 64; kk++) {
            float4 w = *(float4*)&Vs[kk * 68 + tc * 4];
            float wv[4] = {w.x, w.y, w.z, w.w};
#pragma unroll
            for (int i = 0; i < 4; i++) {
                float a = Ps[(tr * 4 + i) * 68 + kk];
#pragma unroll
                for (int j = 0; j < 4; j++)
                    acc[i][j] = fmaf(a, wv[j], acc[i][j]);
            }
        }
    }

    // Write context
#pragma unroll
    for (int i = 0; i < 4; i++) {
        float inv = 1.f / lsum[i];
        float4 o = make_float4(acc[i][0] * inv, acc[i][1] * inv,
                               acc[i][2] * inv, acc[i][3] * inv);
        *(float4*)&g_ctx[(size_t)(b * S_ + qt * 64 + tr * 4 + i) * DIN + h * HD + tc * 4] = o;
    }
}

// ---------------------------------------------------------------------------
// KV-cache output: [b,s,g,d] -> [b,g,s,d]
// ---------------------------------------------------------------------------
__global__ __launch_bounds__(256) void kv_transpose(float* __restrict__ keys,
                                                    float* __restrict__ vals)
{
    int idx = blockIdx.x * blockDim.x + threadIdx.x;   // over B*G*S*HD = 2^21
    int d = idx & 63;
    int s = (idx >> 6) & (S_ - 1);
    int g = (idx >> 17) & (G_ - 1);
    int b = idx >> 20;
    size_t src = (size_t)(b * S_ + s) * DKV + g * HD + d;
    keys[idx] = g_K[src];
    vals[idx] = g_V[src];
}

// ---------------------------------------------------------------------------
extern "C" void kernel_launch(void* const* d_in, const int* in_sizes, int n_in,
                              void* d_out, int out_size)
{
    const float* x  = (const float*)d_in[0];
    const float* Wq = (const float*)d_in[1];
    const float* Wk = (const float*)d_in[2];
    const float* Wv = (const float*)d_in[3];
    const float* Wo = (const float*)d_in[4];

    float* out  = (float*)d_out;
    float* keys = out + (size_t)MROWS * DIN;                 // 8388608
    float* vals = keys + (size_t)B_ * G_ * S_ * HD;          // +2097152

    float *q, *k, *v, *ctx;
    cudaGetSymbolAddress((void**)&q,   g_Q);
    cudaGetSymbolAddress((void**)&k,   g_K);
    cudaGetSymbolAddress((void**)&v,   g_V);
    cudaGetSymbolAddress((void**)&ctx, g_ctx);

    dim3 blk(256);
    gemm_nt128<<<dim3(DIN / 128, MROWS / 128), blk>>>(x, Wq, q, MROWS, DIN, DIN);
    gemm_nt128<<<dim3(DKV / 128, MROWS / 128), blk>>>(x, Wk, k, MROWS, DKV, DIN);
    gemm_nt128<<<dim3(DKV / 128, MROWS / 128), blk>>>(x, Wv, v, MROWS, DKV, DIN);

    size_t shm = 4 * 64 * 68 * sizeof(float);   // 69632
    cudaFuncSetAttribute(attn_kernel, cudaFuncAttributeMaxDynamicSharedMemorySize, (int)shm);
    attn_kernel<<<dim3(S_ / 64, H_, B_), blk, shm>>>();

    gemm_nt128<<<dim3(DIN / 128, MROWS / 128), blk>>>(ctx, Wo, out, MROWS, DIN, DIN);

    kv_transpose<<<(B_ * G_ * S_ * HD) / 256, 256>>>(keys, vals);
}

// round 5
// speedup vs baseline: 1.8360x; 1.8360x over previous
#include <cuda_runtime.h>
#include <cstdint>
#include <math.h>

#define B_   2
#define S_   2048
#define DIN  2048
#define H_   32
#define G_   8
#define R_   4
#define HD   64
#define DKV  512            // G_*HD
#define MROWS (B_*S_)       // 4096

// ---------------------------------------------------------------------------
// Device-global scratch (allocation-free rule)
// ---------------------------------------------------------------------------
__device__ float g_Q[(size_t)MROWS*DIN];
__device__ float g_K[(size_t)MROWS*DKV];
__device__ float g_V[(size_t)MROWS*DKV];
__device__ float g_ctx[(size_t)MROWS*DIN];
__device__ float g_xr [(size_t)MROWS*DIN];
__device__ float g_Wqr[(size_t)DIN*DIN];
__device__ float g_Wkr[(size_t)DKV*DIN];
__device__ float g_Wvr[(size_t)DKV*DIN];
__device__ float g_Wor[(size_t)DIN*DIN];

// ---------------------------------------------------------------------------
// helpers
// ---------------------------------------------------------------------------
__device__ __forceinline__ uint32_t smem_u32(const void* p) {
    uint32_t a;
    asm("{ .reg .u64 t; cvta.to.shared.u64 t, %1; cvt.u32.u64 %0, t; }" : "=r"(a) : "l"(p));
    return a;
}
__device__ __forceinline__ void cp_async16(uint32_t dst, const void* src) {
    asm volatile("cp.async.cg.shared.global [%0], [%1], 16;" :: "r"(dst), "l"(src) : "memory");
}
#define CP_COMMIT()  asm volatile("cp.async.commit_group;" ::: "memory")

__device__ __forceinline__ void mma_tf32(float* d, const float* a, const float* b) {
    asm volatile(
        "mma.sync.aligned.m16n8k8.row.col.f32.tf32.tf32.f32 "
        "{%0,%1,%2,%3}, {%4,%5,%6,%7}, {%8,%9}, {%0,%1,%2,%3};"
        : "+f"(d[0]), "+f"(d[1]), "+f"(d[2]), "+f"(d[3])
        : "r"(__float_as_uint(a[0])), "r"(__float_as_uint(a[1])),
          "r"(__float_as_uint(a[2])), "r"(__float_as_uint(a[3])),
          "r"(__float_as_uint(b[0])), "r"(__float_as_uint(b[1])));
}

// ---------------------------------------------------------------------------
// Round fp32 -> tf32 (rna)
// ---------------------------------------------------------------------------
__global__ __launch_bounds__(256) void round_tf32(const float* __restrict__ in,
                                                  float* __restrict__ out, int n4) {
    int i = blockIdx.x * 256 + threadIdx.x;
    if (i >= n4) return;
    float4 v = *(const float4*)(in + (size_t)i * 4);
    asm("cvt.rna.tf32.f32 %0, %0;" : "+f"(v.x));
    asm("cvt.rna.tf32.f32 %0, %0;" : "+f"(v.y));
    asm("cvt.rna.tf32.f32 %0, %0;" : "+f"(v.z));
    asm("cvt.rna.tf32.f32 %0, %0;" : "+f"(v.w));
    *(float4*)(out + (size_t)i * 4) = v;
}

// ---------------------------------------------------------------------------
// tf32 mma.sync GEMM: C[M,N] = A[M,2048] @ W[N,2048]^T
// CTA 128x128, BK=32, 256 thr (8 warps, 2m x 4n), warp tile 64x32.
// Smem row-major [row][36] (pad 4 floats -> conflict-free frag LDS), double buf.
// ---------------------------------------------------------------------------
#define BK      32
#define NCH     (DIN / BK)          // 64
#define SROW    36                  // floats per smem row (32 + 4 pad)
#define STAGEF  (2 * 128 * SROW)    // floats per stage (A + B)
#define SMEM_DYN (2 * STAGEF * 4)   // 73728 bytes

__device__ __forceinline__ void g_load(uint32_t sbase, int c, int tid,
                                       const float* __restrict__ A,
                                       const float* __restrict__ W,
                                       int bm, int bn) {
    const uint32_t sA = sbase + (uint32_t)(c & 1) * (STAGEF * 4);
    const uint32_t sB = sA + 128 * SROW * 4;
    const float* gA = A + (size_t)bm * DIN + c * BK;
    const float* gB = W + (size_t)bn * DIN + c * BK;
#pragma unroll
    for (int i = 0; i < 4; i++) {
        int idx = tid + i * 256;          // 0..1023
        int r = idx >> 3, j = idx & 7;
        cp_async16(sA + r * (SROW * 4) + j * 16, gA + (size_t)r * DIN + j * 4);
    }
#pragma unroll
    for (int i = 0; i < 4; i++) {
        int idx = tid + i * 256;
        int r = idx >> 3, j = idx & 7;
        cp_async16(sB + r * (SROW * 4) + j * 16, gB + (size_t)r * DIN + j * 4);
    }
}

__global__ __launch_bounds__(256) void gemm_tc(const float* __restrict__ A,
                                               const float* __restrict__ W,
                                               float* __restrict__ C, int ldc) {
    extern __shared__ float dsm[];
    const int tid  = threadIdx.x;
    const int wid  = tid >> 5;
    const int lane = tid & 31;
    const int wm   = wid & 1;         // 0..1  (64-row slab)
    const int wn   = wid >> 1;        // 0..3  (32-col slab)
    const int lr   = lane >> 2;       // 0..7
    const int lc   = lane & 3;        // 0..3
    const int bm   = blockIdx.y * 128;
    const int bn   = blockIdx.x * 128;
    const uint32_t sbase = smem_u32(dsm);

    float acc[4][4][4];
#pragma unroll
    for (int mt = 0; mt < 4; mt++)
#pragma unroll
        for (int nt = 0; nt < 4; nt++)
#pragma unroll
            for (int r = 0; r < 4; r++) acc[mt][nt][r] = 0.f;

    g_load(sbase, 0, tid, A, W, bm, bn);
    CP_COMMIT();

    for (int c = 0; c < NCH; c++) {
        if (c + 1 < NCH) {
            g_load(sbase, c + 1, tid, A, W, bm, bn);
            CP_COMMIT();
            asm volatile("cp.async.wait_group 1;" ::: "memory");
        } else {
            asm volatile("cp.async.wait_group 0;" ::: "memory");
        }
        __syncthreads();

        const float* As = dsm + (c & 1) * STAGEF;           // [128][36]
        const float* Bs = As + 128 * SROW;                  // [128][36]
#pragma unroll
        for (int ks = 0; ks < 4; ks++) {
            const int k0 = ks * 8;
            float af[4][4], bf[4][2];
#pragma unroll
            for (int mt = 0; mt < 4; mt++) {
                const float* ar = As + (wm * 64 + mt * 16 + lr) * SROW + k0 + lc;
                af[mt][0] = ar[0];
                af[mt][1] = ar[8 * SROW];
                af[mt][2] = ar[4];
                af[mt][3] = ar[8 * SROW + 4];
            }
#pragma unroll
            for (int nt = 0; nt < 4; nt++) {
                const float* br = Bs + (wn * 32 + nt * 8 + lr) * SROW + k0 + lc;
                bf[nt][0] = br[0];
                bf[nt][1] = br[4];
            }
#pragma unroll
            for (int mt = 0; mt < 4; mt++)
#pragma unroll
                for (int nt = 0; nt < 4; nt++)
                    mma_tf32(acc[mt][nt], af[mt], bf[nt]);
        }
        __syncthreads();
    }

    // Epilogue: c0,c1 -> (row, col..col+1); c2,c3 -> (row+8, ...)
#pragma unroll
    for (int mt = 0; mt < 4; mt++) {
        const int row = bm + wm * 64 + mt * 16 + lr;
#pragma unroll
        for (int nt = 0; nt < 4; nt++) {
            const int col = bn + wn * 32 + nt * 8 + 2 * lc;
            *(float2*)&C[(size_t)row * ldc + col] =
                make_float2(acc[mt][nt][0], acc[mt][nt][1]);
            *(float2*)&C[(size_t)(row + 8) * ldc + col] =
                make_float2(acc[mt][nt][2], acc[mt][nt][3]);
        }
    }
}

// ---------------------------------------------------------------------------
// Flash attention (causal, fp32) — unchanged
// ---------------------------------------------------------------------------
__global__ __launch_bounds__(256) void attn_kernel()
{
    extern __shared__ float sm[];
    float* Qt = sm;
    float* Kt = Qt + 64 * 68;
    float* Vs = Kt + 64 * 68;
    float* Ps = Vs + 64 * 68;

    const int qt = blockIdx.x;
    const int h  = blockIdx.y;
    const int b  = blockIdx.z;
    const int g  = h / R_;
    const int tid = threadIdx.x;
    const int tr = tid >> 4;
    const int tc = tid & 15;
    const float scale = 0.125f;

#pragma unroll
    for (int l = 0; l < 4; l++) {
        int f  = tid + l * 256;
        int r  = f >> 4;
        int dc = (f & 15) * 4;
        float4 v = *(const float4*)&g_Q[(size_t)(b * S_ + qt * 64 + r) * DIN + h * HD + dc];
        Qt[(dc + 0) * 68 + r] = v.x; Qt[(dc + 1) * 68 + r] = v.y;
        Qt[(dc + 2) * 68 + r] = v.z; Qt[(dc + 3) * 68 + r] = v.w;
    }

    float m[4], lsum[4], acc[4][4];
#pragma unroll
    for (int i = 0; i < 4; i++) {
        m[i] = -1e30f; lsum[i] = 0.f;
#pragma unroll
        for (int j = 0; j < 4; j++) acc[i][j] = 0.f;
    }

    for (int kt = 0; kt <= qt; kt++) {
        __syncthreads();
#pragma unroll
        for (int l = 0; l < 4; l++) {
            int f  = tid + l * 256;
            int r  = f >> 4;
            int dc = (f & 15) * 4;
            size_t src = (size_t)(b * S_ + kt * 64 + r) * DKV + g * HD + dc;
            float4 kv = *(const float4*)&g_K[src];
            Kt[(dc + 0) * 68 + r] = kv.x; Kt[(dc + 1) * 68 + r] = kv.y;
            Kt[(dc + 2) * 68 + r] = kv.z; Kt[(dc + 3) * 68 + r] = kv.w;
            float4 vv = *(const float4*)&g_V[src];
            *(float4*)&Vs[r * 68 + dc] = vv;
        }
        __syncthreads();

        float s[4][4];
#pragma unroll
        for (int i = 0; i < 4; i++)
#pragma unroll
            for (int j = 0; j < 4; j++) s[i][j] = 0.f;
#pragma unroll 8
        for (int dd = 0; dd < 64; dd++) {
            float4 a = *(float4*)&Qt[dd * 68 + tr * 4];
            float4 w = *(float4*)&Kt[dd * 68 + tc * 4];
            float av[4] = {a.x, a.y, a.z, a.w};
            float wv[4] = {w.x, w.y, w.z, w.w};
#pragma unroll
            for (int i = 0; i < 4; i++)
#pragma unroll
                for (int j = 0; j < 4; j++)
                    s[i][j] = fmaf(av[i], wv[j], s[i][j]);
        }

#pragma unroll
        for (int i = 0; i < 4; i++)
#pragma unroll
            for (int j = 0; j < 4; j++) {
                s[i][j] *= scale;
                if (kt == qt && (tc * 4 + j) > (tr * 4 + i)) s[i][j] = -1e30f;
            }

#pragma unroll
        for (int i = 0; i < 4; i++) {
            float rmax = fmaxf(fmaxf(s[i][0], s[i][1]), fmaxf(s[i][2], s[i][3]));
#pragma unroll
            for (int off = 8; off > 0; off >>= 1)
                rmax = fmaxf(rmax, __shfl_xor_sync(0xffffffffu, rmax, off));
            float mn = fmaxf(m[i], rmax);
            float alpha = __expf(m[i] - mn);
            float4 p;
            p.x = __expf(s[i][0] - mn);
            p.y = __expf(s[i][1] - mn);
            p.z = __expf(s[i][2] - mn);
            p.w = __expf(s[i][3] - mn);
            float rsum = p.x + p.y + p.z + p.w;
#pragma unroll
            for (int off = 8; off > 0; off >>= 1)
                rsum += __shfl_xor_sync(0xffffffffu, rsum, off);
            lsum[i] = lsum[i] * alpha + rsum;
            m[i] = mn;
#pragma unroll
            for (int j = 0; j < 4; j++) acc[i][j] *= alpha;
            *(float4*)&Ps[(tr * 4 + i) * 68 + tc * 4] = p;
        }
        __syncthreads();

#pragma unroll 8
        for (int kk = 0; kk < 64; kk++) {
            float4 w = *(float4*)&Vs[kk * 68 + tc * 4];
            float wv[4] = {w.x, w.y, w.z, w.w};
#pragma unroll
            for (int i = 0; i < 4; i++) {
                float a = Ps[(tr * 4 + i) * 68 + kk];
#pragma unroll
                for (int j = 0; j < 4; j++)
                    acc[i][j] = fmaf(a, wv[j], acc[i][j]);
            }
        }
    }

#pragma unroll
    for (int i = 0; i < 4; i++) {
        float inv = 1.f / lsum[i];
        float4 o = make_float4(acc[i][0] * inv, acc[i][1] * inv,
                               acc[i][2] * inv, acc[i][3] * inv);
        *(float4*)&g_ctx[(size_t)(b * S_ + qt * 64 + tr * 4 + i) * DIN + h * HD + tc * 4] = o;
    }
}

// ---------------------------------------------------------------------------
__global__ __launch_bounds__(256) void kv_transpose(float* __restrict__ keys,
                                                    float* __restrict__ vals)
{
    int idx = blockIdx.x * blockDim.x + threadIdx.x;
    int d = idx & 63;
    int s = (idx >> 6) & (S_ - 1);
    int g = (idx >> 17) & (G_ - 1);
    int b = idx >> 20;
    size_t src = (size_t)(b * S_ + s) * DKV + g * HD + d;
    keys[idx] = g_K[src];
    vals[idx] = g_V[src];
}

// ---------------------------------------------------------------------------
extern "C" void kernel_launch(void* const* d_in, const int* in_sizes, int n_in,
                              void* d_out, int out_size)
{
    const float* x  = (const float*)d_in[0];
    const float* Wq = (const float*)d_in[1];
    const float* Wk = (const float*)d_in[2];
    const float* Wv = (const float*)d_in[3];
    const float* Wo = (const float*)d_in[4];

    float* out  = (float*)d_out;
    float* keys = out + (size_t)MROWS * DIN;
    float* vals = keys + (size_t)B_ * G_ * S_ * HD;

    float *q, *k, *v, *ctx, *xr, *wqr, *wkr, *wvr, *wor;
    cudaGetSymbolAddress((void**)&q,   g_Q);
    cudaGetSymbolAddress((void**)&k,   g_K);
    cudaGetSymbolAddress((void**)&v,   g_V);
    cudaGetSymbolAddress((void**)&ctx, g_ctx);
    cudaGetSymbolAddress((void**)&xr,  g_xr);
    cudaGetSymbolAddress((void**)&wqr, g_Wqr);
    cudaGetSymbolAddress((void**)&wkr, g_Wkr);
    cudaGetSymbolAddress((void**)&wvr, g_Wvr);
    cudaGetSymbolAddress((void**)&wor, g_Wor);

    cudaFuncSetAttribute(gemm_tc, cudaFuncAttributeMaxDynamicSharedMemorySize, SMEM_DYN);

    round_tf32<<<(MROWS*DIN/4 + 255)/256, 256>>>(x,  xr,  MROWS*DIN/4);
    round_tf32<<<(DIN*DIN/4   + 255)/256, 256>>>(Wq, wqr, DIN*DIN/4);
    round_tf32<<<(DKV*DIN/4   + 255)/256, 256>>>(Wk, wkr, DKV*DIN/4);
    round_tf32<<<(DKV*DIN/4   + 255)/256, 256>>>(Wv, wvr, DKV*DIN/4);
    round_tf32<<<(DIN*DIN/4   + 255)/256, 256>>>(Wo, wor, DIN*DIN/4);

    gemm_tc<<<dim3(DIN/128, MROWS/128), 256, SMEM_DYN>>>(xr, wqr, q, DIN);
    gemm_tc<<<dim3(DKV/128, MROWS/128), 256, SMEM_DYN>>>(xr, wkr, k, DKV);
    gemm_tc<<<dim3(DKV/128, MROWS/128), 256, SMEM_DYN>>>(xr, wvr, v, DKV);

    size_t shm = 4 * 64 * 68 * sizeof(float);
    cudaFuncSetAttribute(attn_kernel, cudaFuncAttributeMaxDynamicSharedMemorySize, (int)shm);
    attn_kernel<<<dim3(S_ / 64, H_, B_), 256, shm>>>();

    round_tf32<<<(MROWS*DIN/4 + 255)/256, 256>>>(ctx, ctx, MROWS*DIN/4);
    gemm_tc<<<dim3(DIN/128, MROWS/128), 256, SMEM_DYN>>>(ctx, wor, out, DIN);

    kv_transpose<<<(B_ * G_ * S_ * HD) / 256, 256>>>(keys, vals);
}

// round 7
// speedup vs baseline: 3.1442x; 1.7125x over previous
#include <cuda_runtime.h>
#include <cstdint>
#include <math.h>

#define B_   2
#define S_   2048
#define DIN  2048
#define H_   32
#define G_   8
#define R_   4
#define HD   64
#define DKV  512            // G_*HD
#define MROWS (B_*S_)       // 4096

// ---------------------------------------------------------------------------
// Device-global scratch (allocation-free rule)
// ---------------------------------------------------------------------------
__device__ float g_Q[(size_t)MROWS*DIN];
__device__ float g_K[(size_t)MROWS*DKV];
__device__ float g_V[(size_t)MROWS*DKV];
__device__ float g_ctx[(size_t)MROWS*DIN];
__device__ float g_xr [(size_t)MROWS*DIN];
__device__ float g_Wqr[(size_t)DIN*DIN];
__device__ float g_Wkr[(size_t)DKV*DIN];
__device__ float g_Wvr[(size_t)DKV*DIN];
__device__ float g_Wor[(size_t)DIN*DIN];

// ---------------------------------------------------------------------------
// helpers
// ---------------------------------------------------------------------------
__device__ __forceinline__ uint32_t smem_u32(const void* p) {
    uint32_t a;
    asm("{ .reg .u64 t; cvta.to.shared.u64 t, %1; cvt.u32.u64 %0, t; }" : "=r"(a) : "l"(p));
    return a;
}
__device__ __forceinline__ void cp_async16(uint32_t dst, const void* src) {
    asm volatile("cp.async.cg.shared.global [%0], [%1], 16;" :: "r"(dst), "l"(src) : "memory");
}
#define CP_COMMIT()  asm volatile("cp.async.commit_group;" ::: "memory")

__device__ __forceinline__ void mma_tf32(float* d, const float* a, const float* b) {
    asm volatile(
        "mma.sync.aligned.m16n8k8.row.col.f32.tf32.tf32.f32 "
        "{%0,%1,%2,%3}, {%4,%5,%6,%7}, {%8,%9}, {%0,%1,%2,%3};"
        : "+f"(d[0]), "+f"(d[1]), "+f"(d[2]), "+f"(d[3])
        : "r"(__float_as_uint(a[0])), "r"(__float_as_uint(a[1])),
          "r"(__float_as_uint(a[2])), "r"(__float_as_uint(a[3])),
          "r"(__float_as_uint(b[0])), "r"(__float_as_uint(b[1])));
}
__device__ __forceinline__ float tf32r(float x) {
    asm("cvt.rna.tf32.f32 %0, %0;" : "+f"(x));
    return x;
}
__device__ __forceinline__ float ex2(float x) {
    asm("ex2.approx.f32 %0, %0;" : "+f"(x));
    return x;
}

// ---------------------------------------------------------------------------
// Round fp32 -> tf32 (rna)
// ---------------------------------------------------------------------------
__global__ __launch_bounds__(256) void round_tf32(const float* __restrict__ in,
                                                  float* __restrict__ out, int n4) {
    int i = blockIdx.x * 256 + threadIdx.x;
    if (i >= n4) return;
    float4 v = *(const float4*)(in + (size_t)i * 4);
    v.x = tf32r(v.x); v.y = tf32r(v.y); v.z = tf32r(v.z); v.w = tf32r(v.w);
    *(float4*)(out + (size_t)i * 4) = v;
}

// ---------------------------------------------------------------------------
// tf32 mma.sync GEMM (unchanged, passing): C = A @ W^T
// ---------------------------------------------------------------------------
#define BK      32
#define NCH     (DIN / BK)          // 64
#define SROW    36
#define STAGEF  (2 * 128 * SROW)
#define SMEM_DYN (2 * STAGEF * 4)   // 73728 bytes

__device__ __forceinline__ void g_load(uint32_t sbase, int c, int tid,
                                       const float* __restrict__ A,
                                       const float* __restrict__ W,
                                       int bm, int bn) {
    const uint32_t sA = sbase + (uint32_t)(c & 1) * (STAGEF * 4);
    const uint32_t sB = sA + 128 * SROW * 4;
    const float* gA = A + (size_t)bm * DIN + c * BK;
    const float* gB = W + (size_t)bn * DIN + c * BK;
#pragma unroll
    for (int i = 0; i < 4; i++) {
        int idx = tid + i * 256;
        int r = idx >> 3, j = idx & 7;
        cp_async16(sA + r * (SROW * 4) + j * 16, gA + (size_t)r * DIN + j * 4);
    }
#pragma unroll
    for (int i = 0; i < 4; i++) {
        int idx = tid + i * 256;
        int r = idx >> 3, j = idx & 7;
        cp_async16(sB + r * (SROW * 4) + j * 16, gB + (size_t)r * DIN + j * 4);
    }
}

__global__ __launch_bounds__(256) void gemm_tc(const float* __restrict__ A,
                                               const float* __restrict__ W,
                                               float* __restrict__ C, int ldc) {
    extern __shared__ float dsm[];
    const int tid  = threadIdx.x;
    const int wid  = tid >> 5;
    const int lane = tid & 31;
    const int wm   = wid & 1;
    const int wn   = wid >> 1;
    const int lr   = lane >> 2;
    const int lc   = lane & 3;
    const int bm   = blockIdx.y * 128;
    const int bn   = blockIdx.x * 128;
    const uint32_t sbase = smem_u32(dsm);

    float acc[4][4][4];
#pragma unroll
    for (int mt = 0; mt < 4; mt++)
#pragma unroll
        for (int nt = 0; nt < 4; nt++)
#pragma unroll
            for (int r = 0; r < 4; r++) acc[mt][nt][r] = 0.f;

    g_load(sbase, 0, tid, A, W, bm, bn);
    CP_COMMIT();

    for (int c = 0; c < NCH; c++) {
        if (c + 1 < NCH) {
            g_load(sbase, c + 1, tid, A, W, bm, bn);
            CP_COMMIT();
            asm volatile("cp.async.wait_group 1;" ::: "memory");
        } else {
            asm volatile("cp.async.wait_group 0;" ::: "memory");
        }
        __syncthreads();

        const float* As = dsm + (c & 1) * STAGEF;
        const float* Bs = As + 128 * SROW;
#pragma unroll
        for (int ks = 0; ks < 4; ks++) {
            const int k0 = ks * 8;
            float af[4][4], bf[4][2];
#pragma unroll
            for (int mt = 0; mt < 4; mt++) {
                const float* ar = As + (wm * 64 + mt * 16 + lr) * SROW + k0 + lc;
                af[mt][0] = ar[0];
                af[mt][1] = ar[8 * SROW];
                af[mt][2] = ar[4];
                af[mt][3] = ar[8 * SROW + 4];
            }
#pragma unroll
            for (int nt = 0; nt < 4; nt++) {
                const float* br = Bs + (wn * 32 + nt * 8 + lr) * SROW + k0 + lc;
                bf[nt][0] = br[0];
                bf[nt][1] = br[4];
            }
#pragma unroll
            for (int mt = 0; mt < 4; mt++)
#pragma unroll
                for (int nt = 0; nt < 4; nt++)
                    mma_tf32(acc[mt][nt], af[mt], bf[nt]);
        }
        __syncthreads();
    }

#pragma unroll
    for (int mt = 0; mt < 4; mt++) {
        const int row = bm + wm * 64 + mt * 16 + lr;
#pragma unroll
        for (int nt = 0; nt < 4; nt++) {
            const int col = bn + wn * 32 + nt * 8 + 2 * lc;
            *(float2*)&C[(size_t)row * ldc + col] =
                make_float2(acc[mt][nt][0], acc[mt][nt][1]);
            *(float2*)&C[(size_t)(row + 8) * ldc + col] =
                make_float2(acc[mt][nt][2], acc[mt][nt][3]);
        }
    }
}

// ---------------------------------------------------------------------------
// Tensor-core flash attention (causal, tf32 mma.sync, online softmax)
// CTA: 128 q-rows, 8 warps (16 rows each). kt tiles of 64 keys.
// ---------------------------------------------------------------------------
#define AP 72
#define ATTN_SMEM ((128*AP + 64*AP + 64*AP) * 4)   // 73728 B

__global__ __launch_bounds__(256) void attn_tc()
{
    extern __shared__ float sm[];
    float* PQ = sm;                // 128*72 : Q stage / P
    float* Ks = PQ + 128 * AP;     // 64*72
    float* Vs = Ks + 64 * AP;      // 64*72

    const int qt  = (int)gridDim.x - 1 - (int)blockIdx.x;   // big tiles first
    const int h   = blockIdx.y;
    const int b   = blockIdx.z;
    const int g   = h >> 2;
    const int tid = threadIdx.x;
    const int wid = tid >> 5;
    const int lane = tid & 31;
    const int lr  = lane >> 2;
    const int lc  = lane & 3;

    const float qscale = 0.125f * 1.44269504088896340736f;  // 1/sqrt(64)*log2(e)

    // ---- stage Q (scaled + tf32-rounded): 128 rows x 64 dims = 2048 float4 ----
#pragma unroll
    for (int i = 0; i < 8; i++) {
        int f  = tid + i * 256;           // 0..2047
        int r  = f >> 4;                  // 0..127
        int dc = (f & 15) * 4;            // 0..60
        float4 v = *(const float4*)&g_Q[(size_t)(b * S_ + qt * 128 + r) * DIN + h * HD + dc];
        v.x = tf32r(v.x * qscale); v.y = tf32r(v.y * qscale);
        v.z = tf32r(v.z * qscale); v.w = tf32r(v.w * qscale);
        *(float4*)&PQ[r * AP + dc] = v;
    }
    __syncthreads();

    // ---- preload Q fragments (per warp: rows wid*16 .. +15) ----
    float qf[8][4];
    {
        const float* Qw = PQ + (wid * 16) * AP;
#pragma unroll
        for (int ks = 0; ks < 8; ks++) {
            qf[ks][0] = Qw[lr * AP + ks * 8 + lc];
            qf[ks][1] = Qw[(lr + 8) * AP + ks * 8 + lc];
            qf[ks][2] = Qw[lr * AP + ks * 8 + lc + 4];
            qf[ks][3] = Qw[(lr + 8) * AP + ks * 8 + lc + 4];
        }
    }
    // warp w only touches PQ rows w*16..w*16+15 afterward (as P), so no extra
    // cross-warp barrier is needed before the overwrite.

    float o[8][4];
#pragma unroll
    for (int nt = 0; nt < 8; nt++)
#pragma unroll
        for (int r = 0; r < 4; r++) o[nt][r] = 0.f;
    float m0 = -1e30f, m1 = -1e30f, l0 = 0.f, l1 = 0.f;

    const int row0 = qt * 128 + wid * 16 + lr;   // thread rows: row0, row0+8
    const int nkt  = 2 * qt + 2;

    for (int kt = 0; kt < nkt; kt++) {
        __syncthreads();   // previous PV reads of Ks/Vs done
        // ---- load K/V tile (64 keys x 64 dims), tf32-rounded ----
#pragma unroll
        for (int i = 0; i < 4; i++) {
            int f  = tid + i * 256;
            int r  = f >> 4;
            int dc = (f & 15) * 4;
            size_t src = (size_t)(b * S_ + kt * 64 + r) * DKV + g * HD + dc;
            float4 kv = *(const float4*)&g_K[src];
            kv.x = tf32r(kv.x); kv.y = tf32r(kv.y); kv.z = tf32r(kv.z); kv.w = tf32r(kv.w);
            *(float4*)&Ks[r * AP + dc] = kv;
            float4 vv = *(const float4*)&g_V[src];
            vv.x = tf32r(vv.x); vv.y = tf32r(vv.y); vv.z = tf32r(vv.z); vv.w = tf32r(vv.w);
            *(float4*)&Vs[r * AP + dc] = vv;
        }
        __syncthreads();

        // ---- S = Q @ K^T (log2 domain) ----
        float s[8][4];
#pragma unroll
        for (int nt = 0; nt < 8; nt++)
#pragma unroll
            for (int r = 0; r < 4; r++) s[nt][r] = 0.f;
#pragma unroll
        for (int ks = 0; ks < 8; ks++) {
#pragma unroll
            for (int nt = 0; nt < 8; nt++) {
                float bf[2];
                const float* kr = Ks + (nt * 8 + lr) * AP + ks * 8 + lc;
                bf[0] = kr[0];
                bf[1] = kr[4];
                mma_tf32(s[nt], qf[ks], bf);
            }
        }

        // ---- causal mask (diagonal region only) ----
        if (kt * 64 + 63 > row0) {
#pragma unroll
            for (int nt = 0; nt < 8; nt++) {
                int col = kt * 64 + nt * 8 + 2 * lc;
                if (col     > row0)     s[nt][0] = -1e30f;
                if (col + 1 > row0)     s[nt][1] = -1e30f;
                if (col     > row0 + 8) s[nt][2] = -1e30f;
                if (col + 1 > row0 + 8) s[nt][3] = -1e30f;
            }
        }

        // ---- online softmax (base-2 domain) ----
        float r0 = -1e30f, r1 = -1e30f;
#pragma unroll
        for (int nt = 0; nt < 8; nt++) {
            r0 = fmaxf(r0, fmaxf(s[nt][0], s[nt][1]));
            r1 = fmaxf(r1, fmaxf(s[nt][2], s[nt][3]));
        }
        r0 = fmaxf(r0, __shfl_xor_sync(0xffffffffu, r0, 1));
        r0 = fmaxf(r0, __shfl_xor_sync(0xffffffffu, r0, 2));
        r1 = fmaxf(r1, __shfl_xor_sync(0xffffffffu, r1, 1));
        r1 = fmaxf(r1, __shfl_xor_sync(0xffffffffu, r1, 2));
        float mn0 = fmaxf(m0, r0), mn1 = fmaxf(m1, r1);
        float a0 = ex2(m0 - mn0), a1 = ex2(m1 - mn1);
        m0 = mn0; m1 = mn1;

        float* Pw = PQ + (wid * 16) * AP;
        float ps0 = 0.f, ps1 = 0.f;
#pragma unroll
        for (int nt = 0; nt < 8; nt++) {
            float p00 = tf32r(ex2(s[nt][0] - mn0));
            float p01 = tf32r(ex2(s[nt][1] - mn0));
            float p10 = tf32r(ex2(s[nt][2] - mn1));
            float p11 = tf32r(ex2(s[nt][3] - mn1));
            ps0 += p00 + p01;
            ps1 += p10 + p11;
            *(float2*)&Pw[lr * AP + nt * 8 + 2 * lc]       = make_float2(p00, p01);
            *(float2*)&Pw[(lr + 8) * AP + nt * 8 + 2 * lc] = make_float2(p10, p11);
            o[nt][0] *= a0; o[nt][1] *= a0;
            o[nt][2] *= a1; o[nt][3] *= a1;
        }
        ps0 += __shfl_xor_sync(0xffffffffu, ps0, 1);
        ps0 += __shfl_xor_sync(0xffffffffu, ps0, 2);
        ps1 += __shfl_xor_sync(0xffffffffu, ps1, 1);
        ps1 += __shfl_xor_sync(0xffffffffu, ps1, 2);
        l0 = l0 * a0 + ps0;
        l1 = l1 * a1 + ps1;
        __syncwarp();

        // ---- ctx += P @ V ----
#pragma unroll
        for (int ks = 0; ks < 8; ks++) {
            float af[4];
            af[0] = Pw[lr * AP + ks * 8 + lc];
            af[1] = Pw[(lr + 8) * AP + ks * 8 + lc];
            af[2] = Pw[lr * AP + ks * 8 + lc + 4];
            af[3] = Pw[(lr + 8) * AP + ks * 8 + lc + 4];
#pragma unroll
            for (int nt = 0; nt < 8; nt++) {
                float bf[2];
                bf[0] = Vs[(ks * 8 + lc) * AP + nt * 8 + lr];
                bf[1] = Vs[(ks * 8 + lc + 4) * AP + nt * 8 + lr];
                mma_tf32(o[nt], af, bf);
            }
        }
    }

    // ---- normalize + write context ----
    const float i0 = 1.f / l0, i1 = 1.f / l1;
#pragma unroll
    for (int nt = 0; nt < 8; nt++) {
        size_t d0 = (size_t)(b * S_ + row0) * DIN + h * HD + nt * 8 + 2 * lc;
        size_t d1 = (size_t)(b * S_ + row0 + 8) * DIN + h * HD + nt * 8 + 2 * lc;
        *(float2*)&g_ctx[d0] = make_float2(o[nt][0] * i0, o[nt][1] * i0);
        *(float2*)&g_ctx[d1] = make_float2(o[nt][2] * i1, o[nt][3] * i1);
    }
}

// ---------------------------------------------------------------------------
__global__ __launch_bounds__(256) void kv_transpose(float* __restrict__ keys,
                                                    float* __restrict__ vals)
{
    int idx = blockIdx.x * blockDim.x + threadIdx.x;
    int d = idx & 63;
    int s = (idx >> 6) & (S_ - 1);
    int g = (idx >> 17) & (G_ - 1);
    int b = idx >> 20;
    size_t src = (size_t)(b * S_ + s) * DKV + g * HD + d;
    keys[idx] = g_K[src];
    vals[idx] = g_V[src];
}

// ---------------------------------------------------------------------------
extern "C" void kernel_launch(void* const* d_in, const int* in_sizes, int n_in,
                              void* d_out, int out_size)
{
    const float* x  = (const float*)d_in[0];
    const float* Wq = (const float*)d_in[1];
    const float* Wk = (const float*)d_in[2];
    const float* Wv = (const float*)d_in[3];
    const float* Wo = (const float*)d_in[4];

    float* out  = (float*)d_out;
    float* keys = out + (size_t)MROWS * DIN;
    float* vals = keys + (size_t)B_ * G_ * S_ * HD;

    float *q, *k, *v, *ctx, *xr, *wqr, *wkr, *wvr, *wor;
    cudaGetSymbolAddress((void**)&q,   g_Q);
    cudaGetSymbolAddress((void**)&k,   g_K);
    cudaGetSymbolAddress((void**)&v,   g_V);
    cudaGetSymbolAddress((void**)&ctx, g_ctx);
    cudaGetSymbolAddress((void**)&xr,  g_xr);
    cudaGetSymbolAddress((void**)&wqr, g_Wqr);
    cudaGetSymbolAddress((void**)&wkr, g_Wkr);
    cudaGetSymbolAddress((void**)&wvr, g_Wvr);
    cudaGetSymbolAddress((void**)&wor, g_Wor);

    cudaFuncSetAttribute(gemm_tc,  cudaFuncAttributeMaxDynamicSharedMemorySize, SMEM_DYN);
    cudaFuncSetAttribute(attn_tc,  cudaFuncAttributeMaxDynamicSharedMemorySize, ATTN_SMEM);

    round_tf32<<<(MROWS*DIN/4 + 255)/256, 256>>>(x,  xr,  MROWS*DIN/4);
    round_tf32<<<(DIN*DIN/4   + 255)/256, 256>>>(Wq, wqr, DIN*DIN/4);
    round_tf32<<<(DKV*DIN/4   + 255)/256, 256>>>(Wk, wkr, DKV*DIN/4);
    round_tf32<<<(DKV*DIN/4   + 255)/256, 256>>>(Wv, wvr, DKV*DIN/4);
    round_tf32<<<(DIN*DIN/4   + 255)/256, 256>>>(Wo, wor, DIN*DIN/4);

    gemm_tc<<<dim3(DIN/128, MROWS/128), 256, SMEM_DYN>>>(xr, wqr, q, DIN);
    gemm_tc<<<dim3(DKV/128, MROWS/128), 256, SMEM_DYN>>>(xr, wkr, k, DKV);
    gemm_tc<<<dim3(DKV/128, MROWS/128), 256, SMEM_DYN>>>(xr, wvr, v, DKV);

    attn_tc<<<dim3(S_/128, H_, B_), 256, ATTN_SMEM>>>();

    round_tf32<<<(MROWS*DIN/4 + 255)/256, 256>>>(ctx, ctx, MROWS*DIN/4);
    gemm_tc<<<dim3(DIN/128, MROWS/128), 256, SMEM_DYN>>>(ctx, wor, out, DIN);

    kv_transpose<<<(B_ * G_ * S_ * HD) / 256, 256>>>(keys, vals);
}

// round 8
// speedup vs baseline: 3.1934x; 1.0157x over previous
#include <cuda_runtime.h>
#include <cstdint>
#include <math.h>

#define B_   2
#define S_   2048
#define DIN  2048
#define H_   32
#define G_   8
#define R_   4
#define HD   64
#define DKV  512            // G_*HD
#define MROWS (B_*S_)       // 4096

// ---------------------------------------------------------------------------
// Device-global scratch (allocation-free rule)
// ---------------------------------------------------------------------------
__device__ float g_Q[(size_t)MROWS*DIN];
__device__ float g_K[(size_t)MROWS*DKV];
__device__ float g_V[(size_t)MROWS*DKV];
__device__ float g_ctx[(size_t)MROWS*DIN];
__device__ float g_xr [(size_t)MROWS*DIN];
__device__ float g_Wqr[(size_t)DIN*DIN];
__device__ float g_Wkr[(size_t)DKV*DIN];
__device__ float g_Wvr[(size_t)DKV*DIN];
__device__ float g_Wor[(size_t)DIN*DIN];

// ---------------------------------------------------------------------------
// helpers
// ---------------------------------------------------------------------------
__device__ __forceinline__ uint32_t smem_u32(const void* p) {
    uint32_t a;
    asm("{ .reg .u64 t; cvta.to.shared.u64 t, %1; cvt.u32.u64 %0, t; }" : "=r"(a) : "l"(p));
    return a;
}
__device__ __forceinline__ void cp_async16(uint32_t dst, const void* src) {
    asm volatile("cp.async.cg.shared.global [%0], [%1], 16;" :: "r"(dst), "l"(src) : "memory");
}
#define CP_COMMIT()  asm volatile("cp.async.commit_group;" ::: "memory")

__device__ __forceinline__ void mma_tf32(float* d, const float* a, const float* b) {
    asm volatile(
        "mma.sync.aligned.m16n8k8.row.col.f32.tf32.tf32.f32 "
        "{%0,%1,%2,%3}, {%4,%5,%6,%7}, {%8,%9}, {%0,%1,%2,%3};"
        : "+f"(d[0]), "+f"(d[1]), "+f"(d[2]), "+f"(d[3])
        : "r"(__float_as_uint(a[0])), "r"(__float_as_uint(a[1])),
          "r"(__float_as_uint(a[2])), "r"(__float_as_uint(a[3])),
          "r"(__float_as_uint(b[0])), "r"(__float_as_uint(b[1])));
}
__device__ __forceinline__ float tf32r(float x) {
    asm("cvt.rna.tf32.f32 %0, %0;" : "+f"(x));
    return x;
}
__device__ __forceinline__ float ex2(float x) {
    asm("ex2.approx.f32 %0, %0;" : "+f"(x));
    return x;
}

// ---------------------------------------------------------------------------
// Round fp32 -> tf32 (rna)
// ---------------------------------------------------------------------------
__global__ __launch_bounds__(256) void round_tf32(const float* __restrict__ in,
                                                  float* __restrict__ out, int n4) {
    int i = blockIdx.x * 256 + threadIdx.x;
    if (i >= n4) return;
    float4 v = *(const float4*)(in + (size_t)i * 4);
    v.x = tf32r(v.x); v.y = tf32r(v.y); v.z = tf32r(v.z); v.w = tf32r(v.w);
    *(float4*)(out + (size_t)i * 4) = v;
}

// ---------------------------------------------------------------------------
// tf32 mma.sync GEMM: C = A @ W^T.  RND: round output to tf32 in epilogue.
// ---------------------------------------------------------------------------
#define BK      32
#define NCH     (DIN / BK)          // 64
#define SROW    36
#define STAGEF  (2 * 128 * SROW)
#define SMEM_DYN (2 * STAGEF * 4)   // 73728 bytes

__device__ __forceinline__ void g_load(uint32_t sbase, int c, int tid,
                                       const float* __restrict__ A,
                                       const float* __restrict__ W,
                                       int bm, int bn) {
    const uint32_t sA = sbase + (uint32_t)(c & 1) * (STAGEF * 4);
    const uint32_t sB = sA + 128 * SROW * 4;
    const float* gA = A + (size_t)bm * DIN + c * BK;
    const float* gB = W + (size_t)bn * DIN + c * BK;
#pragma unroll
    for (int i = 0; i < 4; i++) {
        int idx = tid + i * 256;
        int r = idx >> 3, j = idx & 7;
        cp_async16(sA + r * (SROW * 4) + j * 16, gA + (size_t)r * DIN + j * 4);
    }
#pragma unroll
    for (int i = 0; i < 4; i++) {
        int idx = tid + i * 256;
        int r = idx >> 3, j = idx & 7;
        cp_async16(sB + r * (SROW * 4) + j * 16, gB + (size_t)r * DIN + j * 4);
    }
}

template <bool RND>
__global__ __launch_bounds__(256) void gemm_tc(const float* __restrict__ A,
                                               const float* __restrict__ W,
                                               float* __restrict__ C, int ldc) {
    extern __shared__ float dsm[];
    const int tid  = threadIdx.x;
    const int wid  = tid >> 5;
    const int lane = tid & 31;
    const int wm   = wid & 1;
    const int wn   = wid >> 1;
    const int lr   = lane >> 2;
    const int lc   = lane & 3;
    const int bm   = blockIdx.y * 128;
    const int bn   = blockIdx.x * 128;
    const uint32_t sbase = smem_u32(dsm);

    float acc[4][4][4];
#pragma unroll
    for (int mt = 0; mt < 4; mt++)
#pragma unroll
        for (int nt = 0; nt < 4; nt++)
#pragma unroll
            for (int r = 0; r < 4; r++) acc[mt][nt][r] = 0.f;

    g_load(sbase, 0, tid, A, W, bm, bn);
    CP_COMMIT();

    for (int c = 0; c < NCH; c++) {
        if (c + 1 < NCH) {
            g_load(sbase, c + 1, tid, A, W, bm, bn);
            CP_COMMIT();
            asm volatile("cp.async.wait_group 1;" ::: "memory");
        } else {
            asm volatile("cp.async.wait_group 0;" ::: "memory");
        }
        __syncthreads();

        const float* As = dsm + (c & 1) * STAGEF;
        const float* Bs = As + 128 * SROW;
#pragma unroll
        for (int ks = 0; ks < 4; ks++) {
            const int k0 = ks * 8;
            float af[4][4], bf[4][2];
#pragma unroll
            for (int mt = 0; mt < 4; mt++) {
                const float* ar = As + (wm * 64 + mt * 16 + lr) * SROW + k0 + lc;
                af[mt][0] = ar[0];
                af[mt][1] = ar[8 * SROW];
                af[mt][2] = ar[4];
                af[mt][3] = ar[8 * SROW + 4];
            }
#pragma unroll
            for (int nt = 0; nt < 4; nt++) {
                const float* br = Bs + (wn * 32 + nt * 8 + lr) * SROW + k0 + lc;
                bf[nt][0] = br[0];
                bf[nt][1] = br[4];
            }
#pragma unroll
            for (int mt = 0; mt < 4; mt++)
#pragma unroll
                for (int nt = 0; nt < 4; nt++)
                    mma_tf32(acc[mt][nt], af[mt], bf[nt]);
        }
        __syncthreads();
    }

#pragma unroll
    for (int mt = 0; mt < 4; mt++) {
        const int row = bm + wm * 64 + mt * 16 + lr;
#pragma unroll
        for (int nt = 0; nt < 4; nt++) {
            const int col = bn + wn * 32 + nt * 8 + 2 * lc;
            float v0 = acc[mt][nt][0], v1 = acc[mt][nt][1];
            float v2 = acc[mt][nt][2], v3 = acc[mt][nt][3];
            if (RND) { v0 = tf32r(v0); v1 = tf32r(v1); v2 = tf32r(v2); v3 = tf32r(v3); }
            *(float2*)&C[(size_t)row * ldc + col]       = make_float2(v0, v1);
            *(float2*)&C[(size_t)(row + 8) * ldc + col] = make_float2(v2, v3);
        }
    }
}

// ---------------------------------------------------------------------------
// Tensor-core flash attention (causal, tf32 mma.sync, online softmax)
// CTA: 128 q-rows, 8 warps. kt tiles of 64 keys, double-buffered cp.async K/V.
// Smem: PQ[128][72] + 2 x (Ks[64][72], Vs[64][72]) = 110592 B.
// ---------------------------------------------------------------------------
#define AP 72
#define KVST (64 * AP)
#define ATTN_SMEM ((128*AP + 4*KVST) * 4)   // 110592 B

__device__ __forceinline__ void kv_load(uint32_t sKs, uint32_t sVs,
                                        int b, int g, int kt, int tid) {
#pragma unroll
    for (int i = 0; i < 4; i++) {
        int f  = tid + i * 256;          // 0..1023
        int r  = f >> 4;                 // 0..63
        int dc = (f & 15) * 4;           // 0..60
        size_t src = (size_t)(b * S_ + kt * 64 + r) * DKV + g * HD + dc;
        uint32_t off = (uint32_t)(r * AP + dc) * 4;
        cp_async16(sKs + off, &g_K[src]);
        cp_async16(sVs + off, &g_V[src]);
    }
}

__global__ __launch_bounds__(256) void attn_tc()
{
    extern __shared__ float sm[];
    float* PQ = sm;                       // 128*72 : Q stage / P

    const int qt  = (int)gridDim.x - 1 - (int)blockIdx.x;   // big tiles first
    const int h   = blockIdx.y;
    const int b   = blockIdx.z;
    const int g   = h >> 2;
    const int tid = threadIdx.x;
    const int wid = tid >> 5;
    const int lane = tid & 31;
    const int lr  = lane >> 2;
    const int lc  = lane & 3;

    const uint32_t sKV0 = smem_u32(sm + 128 * AP);

    const float qscale = 0.125f * 1.44269504088896340736f;  // 1/sqrt(64)*log2(e)
    const int nkt = 2 * qt + 2;

    // prefetch K/V tile 0 (stage 0)
    kv_load(sKV0, sKV0 + KVST * 4, b, g, 0, tid);
    CP_COMMIT();

    // ---- stage Q (scaled + tf32-rounded): 128 rows x 64 dims ----
#pragma unroll
    for (int i = 0; i < 8; i++) {
        int f  = tid + i * 256;
        int r  = f >> 4;
        int dc = (f & 15) * 4;
        float4 v = *(const float4*)&g_Q[(size_t)(b * S_ + qt * 128 + r) * DIN + h * HD + dc];
        v.x = tf32r(v.x * qscale); v.y = tf32r(v.y * qscale);
        v.z = tf32r(v.z * qscale); v.w = tf32r(v.w * qscale);
        *(float4*)&PQ[r * AP + dc] = v;
    }
    __syncthreads();

    // ---- preload Q fragments ----
    float qf[8][4];
    {
        const float* Qw = PQ + (wid * 16) * AP;
#pragma unroll
        for (int ks = 0; ks < 8; ks++) {
            qf[ks][0] = Qw[lr * AP + ks * 8 + lc];
            qf[ks][1] = Qw[(lr + 8) * AP + ks * 8 + lc];
            qf[ks][2] = Qw[lr * AP + ks * 8 + lc + 4];
            qf[ks][3] = Qw[(lr + 8) * AP + ks * 8 + lc + 4];
        }
    }
    // warp w only touches PQ rows w*16..w*16+15 afterward (as P).

    float o[8][4];
#pragma unroll
    for (int nt = 0; nt < 8; nt++)
#pragma unroll
        for (int r = 0; r < 4; r++) o[nt][r] = 0.f;
    float m0 = -1e30f, m1 = -1e30f, l0 = 0.f, l1 = 0.f;

    const int row0 = qt * 128 + wid * 16 + lr;

    for (int kt = 0; kt < nkt; kt++) {
        const int s = kt & 1;
        // prefetch next tile into other stage (overlaps this tile's compute)
        if (kt + 1 < nkt) {
            uint32_t sN = sKV0 + (uint32_t)(s ^ 1) * (2 * KVST * 4);
            kv_load(sN, sN + KVST * 4, b, g, kt + 1, tid);
            CP_COMMIT();
            asm volatile("cp.async.wait_group 1;" ::: "memory");
        } else {
            asm volatile("cp.async.wait_group 0;" ::: "memory");
        }
        __syncthreads();           // stage s visible to all warps

        const float* Ks = sm + 128 * AP + s * (2 * KVST);
        const float* Vs = Ks + KVST;

        // ---- S = Q @ K^T (log2 domain) ----
        float sc[8][4];
#pragma unroll
        for (int nt = 0; nt < 8; nt++)
#pragma unroll
            for (int r = 0; r < 4; r++) sc[nt][r] = 0.f;
#pragma unroll
        for (int ks = 0; ks < 8; ks++) {
#pragma unroll
            for (int nt = 0; nt < 8; nt++) {
                float bf[2];
                const float* kr = Ks + (nt * 8 + lr) * AP + ks * 8 + lc;
                bf[0] = kr[0];
                bf[1] = kr[4];
                mma_tf32(sc[nt], qf[ks], bf);
            }
        }

        // ---- causal mask (diagonal region only) ----
        if (kt * 64 + 63 > row0) {
#pragma unroll
            for (int nt = 0; nt < 8; nt++) {
                int col = kt * 64 + nt * 8 + 2 * lc;
                if (col     > row0)     sc[nt][0] = -1e30f;
                if (col + 1 > row0)     sc[nt][1] = -1e30f;
                if (col     > row0 + 8) sc[nt][2] = -1e30f;
                if (col + 1 > row0 + 8) sc[nt][3] = -1e30f;
            }
        }

        // ---- online softmax (base-2 domain) ----
        float r0 = -1e30f, r1 = -1e30f;
#pragma unroll
        for (int nt = 0; nt < 8; nt++) {
            r0 = fmaxf(r0, fmaxf(sc[nt][0], sc[nt][1]));
            r1 = fmaxf(r1, fmaxf(sc[nt][2], sc[nt][3]));
        }
        r0 = fmaxf(r0, __shfl_xor_sync(0xffffffffu, r0, 1));
        r0 = fmaxf(r0, __shfl_xor_sync(0xffffffffu, r0, 2));
        r1 = fmaxf(r1, __shfl_xor_sync(0xffffffffu, r1, 1));
        r1 = fmaxf(r1, __shfl_xor_sync(0xffffffffu, r1, 2));
        float mn0 = fmaxf(m0, r0), mn1 = fmaxf(m1, r1);
        float a0 = ex2(m0 - mn0), a1 = ex2(m1 - mn1);
        m0 = mn0; m1 = mn1;

        float* Pw = PQ + (wid * 16) * AP;
        float ps0 = 0.f, ps1 = 0.f;
#pragma unroll
        for (int nt = 0; nt < 8; nt++) {
            float p00 = tf32r(ex2(sc[nt][0] - mn0));
            float p01 = tf32r(ex2(sc[nt][1] - mn0));
            float p10 = tf32r(ex2(sc[nt][2] - mn1));
            float p11 = tf32r(ex2(sc[nt][3] - mn1));
            ps0 += p00 + p01;
            ps1 += p10 + p11;
            *(float2*)&Pw[lr * AP + nt * 8 + 2 * lc]       = make_float2(p00, p01);
            *(float2*)&Pw[(lr + 8) * AP + nt * 8 + 2 * lc] = make_float2(p10, p11);
            o[nt][0] *= a0; o[nt][1] *= a0;
            o[nt][2] *= a1; o[nt][3] *= a1;
        }
        ps0 += __shfl_xor_sync(0xffffffffu, ps0, 1);
        ps0 += __shfl_xor_sync(0xffffffffu, ps0, 2);
        ps1 += __shfl_xor_sync(0xffffffffu, ps1, 1);
        ps1 += __shfl_xor_sync(0xffffffffu, ps1, 2);
        l0 = l0 * a0 + ps0;
        l1 = l1 * a1 + ps1;
        __syncwarp();

        // ---- ctx += P @ V ----
#pragma unroll
        for (int ks = 0; ks < 8; ks++) {
            float af[4];
            af[0] = Pw[lr * AP + ks * 8 + lc];
            af[1] = Pw[(lr + 8) * AP + ks * 8 + lc];
            af[2] = Pw[lr * AP + ks * 8 + lc + 4];
            af[3] = Pw[(lr + 8) * AP + ks * 8 + lc + 4];
#pragma unroll
            for (int nt = 0; nt < 8; nt++) {
                float bf[2];
                bf[0] = Vs[(ks * 8 + lc) * AP + nt * 8 + lr];
                bf[1] = Vs[(ks * 8 + lc + 4) * AP + nt * 8 + lr];
                mma_tf32(o[nt], af, bf);
            }
        }
        __syncthreads();           // all warps done with stage s before overwrite
    }

    // ---- normalize + tf32-round + write context ----
    const float i0 = 1.f / l0, i1 = 1.f / l1;
#pragma unroll
    for (int nt = 0; nt < 8; nt++) {
        size_t d0 = (size_t)(b * S_ + row0) * DIN + h * HD + nt * 8 + 2 * lc;
        size_t d1 = (size_t)(b * S_ + row0 + 8) * DIN + h * HD + nt * 8 + 2 * lc;
        *(float2*)&g_ctx[d0] = make_float2(tf32r(o[nt][0] * i0), tf32r(o[nt][1] * i0));
        *(float2*)&g_ctx[d1] = make_float2(tf32r(o[nt][2] * i1), tf32r(o[nt][3] * i1));
    }
}

// ---------------------------------------------------------------------------
__global__ __launch_bounds__(256) void kv_transpose(float* __restrict__ keys,
                                                    float* __restrict__ vals)
{
    int idx = blockIdx.x * blockDim.x + threadIdx.x;
    int d = idx & 63;
    int s = (idx >> 6) & (S_ - 1);
    int g = (idx >> 17) & (G_ - 1);
    int b = idx >> 20;
    size_t src = (size_t)(b * S_ + s) * DKV + g * HD + d;
    keys[idx] = g_K[src];
    vals[idx] = g_V[src];
}

// ---------------------------------------------------------------------------
extern "C" void kernel_launch(void* const* d_in, const int* in_sizes, int n_in,
                              void* d_out, int out_size)
{
    const float* x  = (const float*)d_in[0];
    const float* Wq = (const float*)d_in[1];
    const float* Wk = (const float*)d_in[2];
    const float* Wv = (const float*)d_in[3];
    const float* Wo = (const float*)d_in[4];

    float* out  = (float*)d_out;
    float* keys = out + (size_t)MROWS * DIN;
    float* vals = keys + (size_t)B_ * G_ * S_ * HD;

    float *q, *k, *v, *ctx, *xr, *wqr, *wkr, *wvr, *wor;
    cudaGetSymbolAddress((void**)&q,   g_Q);
    cudaGetSymbolAddress((void**)&k,   g_K);
    cudaGetSymbolAddress((void**)&v,   g_V);
    cudaGetSymbolAddress((void**)&ctx, g_ctx);
    cudaGetSymbolAddress((void**)&xr,  g_xr);
    cudaGetSymbolAddress((void**)&wqr, g_Wqr);
    cudaGetSymbolAddress((void**)&wkr, g_Wkr);
    cudaGetSymbolAddress((void**)&wvr, g_Wvr);
    cudaGetSymbolAddress((void**)&wor, g_Wor);

    cudaFuncSetAttribute(gemm_tc<false>, cudaFuncAttributeMaxDynamicSharedMemorySize, SMEM_DYN);
    cudaFuncSetAttribute(gemm_tc<true>,  cudaFuncAttributeMaxDynamicSharedMemorySize, SMEM_DYN);
    cudaFuncSetAttribute(attn_tc, cudaFuncAttributeMaxDynamicSharedMemorySize, ATTN_SMEM);

    round_tf32<<<(MROWS*DIN/4 + 255)/256, 256>>>(x,  xr,  MROWS*DIN/4);
    round_tf32<<<(DIN*DIN/4   + 255)/256, 256>>>(Wq, wqr, DIN*DIN/4);
    round_tf32<<<(DKV*DIN/4   + 255)/256, 256>>>(Wk, wkr, DKV*DIN/4);
    round_tf32<<<(DKV*DIN/4   + 255)/256, 256>>>(Wv, wvr, DKV*DIN/4);
    round_tf32<<<(DIN*DIN/4   + 255)/256, 256>>>(Wo, wor, DIN*DIN/4);

    gemm_tc<false><<<dim3(DIN/128, MROWS/128), 256, SMEM_DYN>>>(xr, wqr, q, DIN);
    gemm_tc<true> <<<dim3(DKV/128, MROWS/128), 256, SMEM_DYN>>>(xr, wkr, k, DKV);
    gemm_tc<true> <<<dim3(DKV/128, MROWS/128), 256, SMEM_DYN>>>(xr, wvr, v, DKV);

    attn_tc<<<dim3(S_/128, H_, B_), 256, ATTN_SMEM>>>();

    gemm_tc<false><<<dim3(DIN/128, MROWS/128), 256, SMEM_DYN>>>(ctx, wor, out, DIN);

    kv_transpose<<<(B_ * G_ * S_ * HD) / 256, 256>>>(keys, vals);
}

// round 10
// speedup vs baseline: 3.2395x; 1.0144x over previous
#include <cuda_runtime.h>
#include <cstdint>
#include <math.h>

#define B_   2
#define S_   2048
#define DIN  2048
#define H_   32
#define G_   8
#define R_   4
#define HD   64
#define DKV  512            // G_*HD
#define MROWS (B_*S_)       // 4096

// ---------------------------------------------------------------------------
// Device-global scratch (allocation-free rule)
// ---------------------------------------------------------------------------
__device__ float g_Q[(size_t)MROWS*DIN];
__device__ float g_K[(size_t)MROWS*DKV];
__device__ float g_V[(size_t)MROWS*DKV];
__device__ float g_ctx[(size_t)MROWS*DIN];
__device__ float g_xr [(size_t)MROWS*DIN];
__device__ float g_Wqr[(size_t)DIN*DIN];
__device__ float g_Wkr[(size_t)DKV*DIN];
__device__ float g_Wvr[(size_t)DKV*DIN];
__device__ float g_Wor[(size_t)DIN*DIN];

// ---------------------------------------------------------------------------
// helpers
// ---------------------------------------------------------------------------
__device__ __forceinline__ uint32_t smem_u32(const void* p) {
    uint32_t a;
    asm("{ .reg .u64 t; cvta.to.shared.u64 t, %1; cvt.u32.u64 %0, t; }" : "=r"(a) : "l"(p));
    return a;
}
__device__ __forceinline__ void cp_async16(uint32_t dst, const void* src) {
    asm volatile("cp.async.cg.shared.global [%0], [%1], 16;" :: "r"(dst), "l"(src) : "memory");
}
#define CP_COMMIT()  asm volatile("cp.async.commit_group;" ::: "memory")

__device__ __forceinline__ void mma_tf32(float* d, const float* a, const float* b) {
    asm volatile(
        "mma.sync.aligned.m16n8k8.row.col.f32.tf32.tf32.f32 "
        "{%0,%1,%2,%3}, {%4,%5,%6,%7}, {%8,%9}, {%0,%1,%2,%3};"
        : "+f"(d[0]), "+f"(d[1]), "+f"(d[2]), "+f"(d[3])
        : "r"(__float_as_uint(a[0])), "r"(__float_as_uint(a[1])),
          "r"(__float_as_uint(a[2])), "r"(__float_as_uint(a[3])),
          "r"(__float_as_uint(b[0])), "r"(__float_as_uint(b[1])));
}
__device__ __forceinline__ float tf32r(float x) {
    asm("cvt.rna.tf32.f32 %0, %0;" : "+f"(x));
    return x;
}
__device__ __forceinline__ float ex2(float x) {
    asm("ex2.approx.f32 %0, %0;" : "+f"(x));
    return x;
}

// ---------------------------------------------------------------------------
// Round fp32 -> tf32 (rna)
// ---------------------------------------------------------------------------
__global__ __launch_bounds__(256) void round_tf32(const float* __restrict__ in,
                                                  float* __restrict__ out, int n4) {
    int i = blockIdx.x * 256 + threadIdx.x;
    if (i >= n4) return;
    float4 v = *(const float4*)(in + (size_t)i * 4);
    v.x = tf32r(v.x); v.y = tf32r(v.y); v.z = tf32r(v.z); v.w = tf32r(v.w);
    *(float4*)(out + (size_t)i * 4) = v;
}

// ---------------------------------------------------------------------------
// tf32 mma.sync GEMM: C = A @ W^T.
// RND: round output to tf32 in epilogue.
// Ckv: optional second destination in KV-cache layout [b,g,s,d] (K/V gemms).
// ---------------------------------------------------------------------------
#define BK      32
#define NCH     (DIN / BK)          // 64
#define SROW    36
#define STAGEF  (2 * 128 * SROW)
#define SMEM_DYN (2 * STAGEF * 4)   // 73728 bytes

__device__ __forceinline__ void g_load(uint32_t sbase, int c, int tid,
                                       const float* __restrict__ A,
                                       const float* __restrict__ W,
                                       int bm, int bn) {
    const uint32_t sA = sbase + (uint32_t)(c & 1) * (STAGEF * 4);
    const uint32_t sB = sA + 128 * SROW * 4;
    const float* gA = A + (size_t)bm * DIN + c * BK;
    const float* gB = W + (size_t)bn * DIN + c * BK;
#pragma unroll
    for (int i = 0; i < 4; i++) {
        int idx = tid + i * 256;
        int r = idx >> 3, j = idx & 7;
        cp_async16(sA + r * (SROW * 4) + j * 16, gA + (size_t)r * DIN + j * 4);
    }
#pragma unroll
    for (int i = 0; i < 4; i++) {
        int idx = tid + i * 256;
        int r = idx >> 3, j = idx & 7;
        cp_async16(sB + r * (SROW * 4) + j * 16, gB + (size_t)r * DIN + j * 4);
    }
}

template <bool RND>
__global__ __launch_bounds__(256, 2) void gemm_tc(const float* __restrict__ A,
                                                  const float* __restrict__ W,
                                                  float* __restrict__ C, int ldc,
                                                  float* __restrict__ Ckv) {
    extern __shared__ float dsm[];
    const int tid  = threadIdx.x;
    const int wid  = tid >> 5;
    const int lane = tid & 31;
    const int wm   = wid & 1;
    const int wn   = wid >> 1;
    const int lr   = lane >> 2;
    const int lc   = lane & 3;
    const int bm   = blockIdx.y * 128;
    const int bn   = blockIdx.x * 128;
    const uint32_t sbase = smem_u32(dsm);

    float acc[4][4][4];
#pragma unroll
    for (int mt = 0; mt < 4; mt++)
#pragma unroll
        for (int nt = 0; nt < 4; nt++)
#pragma unroll
            for (int r = 0; r < 4; r++) acc[mt][nt][r] = 0.f;

    g_load(sbase, 0, tid, A, W, bm, bn);
    CP_COMMIT();

    for (int c = 0; c < NCH; c++) {
        if (c + 1 < NCH) {
            g_load(sbase, c + 1, tid, A, W, bm, bn);
            CP_COMMIT();
            asm volatile("cp.async.wait_group 1;" ::: "memory");
        } else {
            asm volatile("cp.async.wait_group 0;" ::: "memory");
        }
        __syncthreads();

        const float* As = dsm + (c & 1) * STAGEF;
        const float* Bs = As + 128 * SROW;
#pragma unroll
        for (int ks = 0; ks < 4; ks++) {
            const int k0 = ks * 8;
            float af[4][4], bf[4][2];
#pragma unroll
            for (int mt = 0; mt < 4; mt++) {
                const float* ar = As + (wm * 64 + mt * 16 + lr) * SROW + k0 + lc;
                af[mt][0] = ar[0];
                af[mt][1] = ar[8 * SROW];
                af[mt][2] = ar[4];
                af[mt][3] = ar[8 * SROW + 4];
            }
#pragma unroll
            for (int nt = 0; nt < 4; nt++) {
                const float* br = Bs + (wn * 32 + nt * 8 + lr) * SROW + k0 + lc;
                bf[nt][0] = br[0];
                bf[nt][1] = br[4];
            }
#pragma unroll
            for (int mt = 0; mt < 4; mt++)
#pragma unroll
                for (int nt = 0; nt < 4; nt++)
                    mma_tf32(acc[mt][nt], af[mt], bf[nt]);
        }
        __syncthreads();
    }

#pragma unroll
    for (int mt = 0; mt < 4; mt++) {
        const int row = bm + wm * 64 + mt * 16 + lr;
#pragma unroll
        for (int nt = 0; nt < 4; nt++) {
            const int col = bn + wn * 32 + nt * 8 + 2 * lc;
            float v0 = acc[mt][nt][0], v1 = acc[mt][nt][1];
            float v2 = acc[mt][nt][2], v3 = acc[mt][nt][3];
            if (RND) { v0 = tf32r(v0); v1 = tf32r(v1); v2 = tf32r(v2); v3 = tf32r(v3); }
            *(float2*)&C[(size_t)row * ldc + col]       = make_float2(v0, v1);
            *(float2*)&C[(size_t)(row + 8) * ldc + col] = make_float2(v2, v3);
            if (Ckv) {
                // KV-cache layout: [b, g, s, d]; row = b*S+s, col = g*64+d
                const int g  = col >> 6;
                const int d  = col & 63;
#pragma unroll
                for (int rr = 0; rr < 2; rr++) {
                    const int r2 = row + rr * 8;
                    const int b  = r2 >> 11;
                    const int s  = r2 & 2047;
                    size_t dst = (((size_t)(b * G_ + g)) * S_ + s) * HD + d;
                    *(float2*)&Ckv[dst] = rr ? make_float2(v2, v3) : make_float2(v0, v1);
                }
            }
        }
    }
}

// ---------------------------------------------------------------------------
// Tensor-core flash attention (causal, tf32 mma.sync, online softmax)
// CTA: 128 q-rows, 8 warps. kt tiles of 64 keys, double-buffered cp.async K/V.
// __launch_bounds__(256, 2): cap regs at 128 so 2 CTAs/SM co-reside.
// ---------------------------------------------------------------------------
#define AP 72
#define KVST (64 * AP)
#define ATTN_SMEM ((128*AP + 4*KVST) * 4)   // 110592 B

__device__ __forceinline__ void kv_load(uint32_t sKs, uint32_t sVs,
                                        int b, int g, int kt, int tid) {
#pragma unroll
    for (int i = 0; i < 4; i++) {
        int f  = tid + i * 256;          // 0..1023
        int r  = f >> 4;                 // 0..63
        int dc = (f & 15) * 4;           // 0..60
        size_t src = (size_t)(b * S_ + kt * 64 + r) * DKV + g * HD + dc;
        uint32_t off = (uint32_t)(r * AP + dc) * 4;
        cp_async16(sKs + off, &g_K[src]);
        cp_async16(sVs + off, &g_V[src]);
    }
}

__global__ __launch_bounds__(256, 2) void attn_tc()
{
    extern __shared__ float sm[];
    float* PQ = sm;                       // 128*72 : Q stage / P

    const int qt  = (int)gridDim.x - 1 - (int)blockIdx.x;   // big tiles first
    const int h   = blockIdx.y;
    const int b   = blockIdx.z;
    const int g   = h >> 2;
    const int tid = threadIdx.x;
    const int wid = tid >> 5;
    const int lane = tid & 31;
    const int lr  = lane >> 2;
    const int lc  = lane & 3;

    const uint32_t sKV0 = smem_u32(sm + 128 * AP);

    const float qscale = 0.125f * 1.44269504088896340736f;  // 1/sqrt(64)*log2(e)
    const int nkt = 2 * qt + 2;

    // prefetch K/V tile 0 (stage 0)
    kv_load(sKV0, sKV0 + KVST * 4, b, g, 0, tid);
    CP_COMMIT();

    // ---- stage Q (scaled + tf32-rounded): 128 rows x 64 dims ----
#pragma unroll
    for (int i = 0; i < 8; i++) {
        int f  = tid + i * 256;
        int r  = f >> 4;
        int dc = (f & 15) * 4;
        float4 v = *(const float4*)&g_Q[(size_t)(b * S_ + qt * 128 + r) * DIN + h * HD + dc];
        v.x = tf32r(v.x * qscale); v.y = tf32r(v.y * qscale);
        v.z = tf32r(v.z * qscale); v.w = tf32r(v.w * qscale);
        *(float4*)&PQ[r * AP + dc] = v;
    }
    __syncthreads();

    // ---- preload Q fragments ----
    float qf[8][4];
    {
        const float* Qw = PQ + (wid * 16) * AP;
#pragma unroll
        for (int ks = 0; ks < 8; ks++) {
            qf[ks][0] = Qw[lr * AP + ks * 8 + lc];
            qf[ks][1] = Qw[(lr + 8) * AP + ks * 8 + lc];
            qf[ks][2] = Qw[lr * AP + ks * 8 + lc + 4];
            qf[ks][3] = Qw[(lr + 8) * AP + ks * 8 + lc + 4];
        }
    }
    // warp w only touches PQ rows w*16..w*16+15 afterward (as P).

    float o[8][4];
#pragma unroll
    for (int nt = 0; nt < 8; nt++)
#pragma unroll
        for (int r = 0; r < 4; r++) o[nt][r] = 0.f;
    float m0 = -1e30f, m1 = -1e30f, l0 = 0.f, l1 = 0.f;

    const int row0 = qt * 128 + wid * 16 + lr;

    for (int kt = 0; kt < nkt; kt++) {
        const int s = kt & 1;
        // prefetch next tile into other stage (overlaps this tile's compute)
        if (kt + 1 < nkt) {
            uint32_t sN = sKV0 + (uint32_t)(s ^ 1) * (2 * KVST * 4);
            kv_load(sN, sN + KVST * 4, b, g, kt + 1, tid);
            CP_COMMIT();
            asm volatile("cp.async.wait_group 1;" ::: "memory");
        } else {
            asm volatile("cp.async.wait_group 0;" ::: "memory");
        }
        __syncthreads();           // stage s visible to all warps

        const float* Ks = sm + 128 * AP + s * (2 * KVST);
        const float* Vs = Ks + KVST;

        // ---- S = Q @ K^T (log2 domain) ----
        float sc[8][4];
#pragma unroll
        for (int nt = 0; nt < 8; nt++)
#pragma unroll
            for (int r = 0; r < 4; r++) sc[nt][r] = 0.f;
#pragma unroll
        for (int ks = 0; ks < 8; ks++) {
#pragma unroll
            for (int nt = 0; nt < 8; nt++) {
                float bf[2];
                const float* kr = Ks + (nt * 8 + lr) * AP + ks * 8 + lc;
                bf[0] = kr[0];
                bf[1] = kr[4];
                mma_tf32(sc[nt], qf[ks], bf);
            }
        }

        // ---- causal mask (diagonal region only) ----
        if (kt * 64 + 63 > row0) {
#pragma unroll
            for (int nt = 0; nt < 8; nt++) {
                int col = kt * 64 + nt * 8 + 2 * lc;
                if (col     > row0)     sc[nt][0] = -1e30f;
                if (col + 1 > row0)     sc[nt][1] = -1e30f;
                if (col     > row0 + 8) sc[nt][2] = -1e30f;
                if (col + 1 > row0 + 8) sc[nt][3] = -1e30f;
            }
        }

        // ---- online softmax (base-2 domain) ----
        float r0 = -1e30f, r1 = -1e30f;
#pragma unroll
        for (int nt = 0; nt < 8; nt++) {
            r0 = fmaxf(r0, fmaxf(sc[nt][0], sc[nt][1]));
            r1 = fmaxf(r1, fmaxf(sc[nt][2], sc[nt][3]));
        }
        r0 = fmaxf(r0, __shfl_xor_sync(0xffffffffu, r0, 1));
        r0 = fmaxf(r0, __shfl_xor_sync(0xffffffffu, r0, 2));
        r1 = fmaxf(r1, __shfl_xor_sync(0xffffffffu, r1, 1));
        r1 = fmaxf(r1, __shfl_xor_sync(0xffffffffu, r1, 2));
        float mn0 = fmaxf(m0, r0), mn1 = fmaxf(m1, r1);
        float a0 = ex2(m0 - mn0), a1 = ex2(m1 - mn1);
        m0 = mn0; m1 = mn1;

        float* Pw = PQ + (wid * 16) * AP;
        float ps0 = 0.f, ps1 = 0.f;
#pragma unroll
        for (int nt = 0; nt < 8; nt++) {
            float p00 = tf32r(ex2(sc[nt][0] - mn0));
            float p01 = tf32r(ex2(sc[nt][1] - mn0));
            float p10 = tf32r(ex2(sc[nt][2] - mn1));
            float p11 = tf32r(ex2(sc[nt][3] - mn1));
            ps0 += p00 + p01;
            ps1 += p10 + p11;
            *(float2*)&Pw[lr * AP + nt * 8 + 2 * lc]       = make_float2(p00, p01);
            *(float2*)&Pw[(lr + 8) * AP + nt * 8 + 2 * lc] = make_float2(p10, p11);
            o[nt][0] *= a0; o[nt][1] *= a0;
            o[nt][2] *= a1; o[nt][3] *= a1;
        }
        ps0 += __shfl_xor_sync(0xffffffffu, ps0, 1);
        ps0 += __shfl_xor_sync(0xffffffffu, ps0, 2);
        ps1 += __shfl_xor_sync(0xffffffffu, ps1, 1);
        ps1 += __shfl_xor_sync(0xffffffffu, ps1, 2);
        l0 = l0 * a0 + ps0;
        l1 = l1 * a1 + ps1;
        __syncwarp();

        // ---- ctx += P @ V ----
#pragma unroll
        for (int ks = 0; ks < 8; ks++) {
            float af[4];
            af[0] = Pw[lr * AP + ks * 8 + lc];
            af[1] = Pw[(lr + 8) * AP + ks * 8 + lc];
            af[2] = Pw[lr * AP + ks * 8 + lc + 4];
            af[3] = Pw[(lr + 8) * AP + ks * 8 + lc + 4];
#pragma unroll
            for (int nt = 0; nt < 8; nt++) {
                float bf[2];
                bf[0] = Vs[(ks * 8 + lc) * AP + nt * 8 + lr];
                bf[1] = Vs[(ks * 8 + lc + 4) * AP + nt * 8 + lr];
                mma_tf32(o[nt], af, bf);
            }
        }
        __syncthreads();           // all warps done with stage s before overwrite
    }

    // ---- normalize + tf32-round + write context ----
    const float i0 = 1.f / l0, i1 = 1.f / l1;
#pragma unroll
    for (int nt = 0; nt < 8; nt++) {
        size_t d0 = (size_t)(b * S_ + row0) * DIN + h * HD + nt * 8 + 2 * lc;
        size_t d1 = (size_t)(b * S_ + row0 + 8) * DIN + h * HD + nt * 8 + 2 * lc;
        *(float2*)&g_ctx[d0] = make_float2(tf32r(o[nt][0] * i0), tf32r(o[nt][1] * i0));
        *(float2*)&g_ctx[d1] = make_float2(tf32r(o[nt][2] * i1), tf32r(o[nt][3] * i1));
    }
}

// ---------------------------------------------------------------------------
extern "C" void kernel_launch(void* const* d_in, const int* in_sizes, int n_in,
                              void* d_out, int out_size)
{
    const float* x  = (const float*)d_in[0];
    const float* Wq = (const float*)d_in[1];
    const float* Wk = (const float*)d_in[2];
    const float* Wv = (const float*)d_in[3];
    const float* Wo = (const float*)d_in[4];

    float* out  = (float*)d_out;
    float* keys = out + (size_t)MROWS * DIN;
    float* vals = keys + (size_t)B_ * G_ * S_ * HD;

    float *q, *k, *v, *ctx, *xr, *wqr, *wkr, *wvr, *wor;
    cudaGetSymbolAddress((void**)&q,   g_Q);
    cudaGetSymbolAddress((void**)&k,   g_K);
    cudaGetSymbolAddress((void**)&v,   g_V);
    cudaGetSymbolAddress((void**)&ctx, g_ctx);
    cudaGetSymbolAddress((void**)&xr,  g_xr);
    cudaGetSymbolAddress((void**)&wqr, g_Wqr);
    cudaGetSymbolAddress((void**)&wkr, g_Wkr);
    cudaGetSymbolAddress((void**)&wvr, g_Wvr);
    cudaGetSymbolAddress((void**)&wor, g_Wor);

    cudaFuncSetAttribute(gemm_tc<false>, cudaFuncAttributeMaxDynamicSharedMemorySize, SMEM_DYN);
    cudaFuncSetAttribute(gemm_tc<true>,  cudaFuncAttributeMaxDynamicSharedMemorySize, SMEM_DYN);
    cudaFuncSetAttribute(attn_tc, cudaFuncAttributeMaxDynamicSharedMemorySize, ATTN_SMEM);

    round_tf32<<<(MROWS*DIN/4 + 255)/256, 256>>>(x,  xr,  MROWS*DIN/4);
    round_tf32<<<(DIN*DIN/4   + 255)/256, 256>>>(Wq, wqr, DIN*DIN/4);
    round_tf32<<<(DKV*DIN/4   + 255)/256, 256>>>(Wk, wkr, DKV*DIN/4);
    round_tf32<<<(DKV*DIN/4   + 255)/256, 256>>>(Wv, wvr, DKV*DIN/4);
    round_tf32<<<(DIN*DIN/4   + 255)/256, 256>>>(Wo, wor, DIN*DIN/4);

    gemm_tc<false><<<dim3(DIN/128, MROWS/128), 256, SMEM_DYN>>>(xr, wqr, q, DIN, nullptr);
    gemm_tc<true> <<<dim3(DKV/128, MROWS/128), 256, SMEM_DYN>>>(xr, wkr, k, DKV, keys);
    gemm_tc<true> <<<dim3(DKV/128, MROWS/128), 256, SMEM_DYN>>>(xr, wvr, v, DKV, vals);

    attn_tc<<<dim3(S_/128, H_, B_), 256, ATTN_SMEM>>>();

    gemm_tc<false><<<dim3(DIN/128, MROWS/128), 256, SMEM_DYN>>>(ctx, wor, out, DIN, nullptr);
}